// round 16
// baseline (speedup 1.0000x reference)
#include <cuda_runtime.h>
#include <math.h>

#define B_ 512
#define T_ 512

// Scratch (static __device__ arrays: allocation-free per harness rules)
__device__ float g_xw0[(size_t)T_ * B_ * 16];   // layer0 input projection [t][b][16]
__device__ float g_hlast[B_ * 70];
__device__ float g_dummy[32];

// ---------------------------------------------------------------------------
// helpers
// ---------------------------------------------------------------------------
__device__ __forceinline__ void ffma2_acc(float2& acc, float2 a, float2 b) {
    asm("fma.rn.f32x2 %0, %1, %2, %0;"
        : "+l"(reinterpret_cast<unsigned long long&>(acc))
        : "l"(reinterpret_cast<const unsigned long long&>(a)),
          "l"(reinterpret_cast<const unsigned long long&>(b)));
}
__device__ __forceinline__ float2 sh2(float2 v, int m) {
    float2 r;
    r.x = __shfl_xor_sync(0xffffffffu, v.x, m);
    r.y = __shfl_xor_sync(0xffffffffu, v.y, m);
    return r;
}
__device__ __forceinline__ float2 add2(float2 a, float2 b) {
    return make_float2(a.x + b.x, a.y + b.y);
}
// tanh(x) = sign(x)*(1 - e^{-2|x|})/(1 + e^{-2|x|}); denom in [1,2]. ~1e-7 abs err.
__device__ __forceinline__ float ftanh(float x) {
    float ax = fabsf(x);
    float t = __expf(-2.f * ax);
    float r = __fdividef(1.f - t, 1.f + t);
    return copysignf(r, x);
}
__device__ __forceinline__ void barn(int id, int cnt) {
    asm volatile("bar.sync %0, %1;" :: "r"(id), "r"(cnt) : "memory");
}
__global__ void dummy_kernel(float* p) { if (threadIdx.x == 0) p[0] = 1.f; }

// ---------------------------------------------------------------------------
// GEMM for layer-0 input projection (round-4 version, measured 62us)
// ---------------------------------------------------------------------------
template <int K, int N, int TM>
__global__ void __launch_bounds__((N / 4) * (TM / 4))
gemm0_kernel(const float* __restrict__ in, const float* __restrict__ W,
             const float* __restrict__ bias, float* __restrict__ out) {
    constexpr int NG4 = N / 4;
    constexpr int TMP = TM + 4;

    __shared__ __align__(16) float AshT[K * TMP];
    __shared__ __align__(16) float Wsh[K * N];

    const int tid  = threadIdx.x;
    const int nthr = blockDim.x;
    const int rM   = blockIdx.x * TM;

#pragma unroll 4
    for (int idx = tid; idx < K * N; idx += nthr) Wsh[idx] = W[idx];
#pragma unroll 8
    for (int idx = tid; idx < TM * K; idx += nthr) {
        int rr = idx / K, kk = idx % K;
        int r = rM + rr;
        int t = r >> 9;
        int b = r & (B_ - 1);
        AshT[kk * TMP + rr] = in[((size_t)b * T_ + t) * K + kk];
    }
    __syncthreads();

    const int tx  = tid % NG4;
    const int rid = tid / NG4;
    const int colb = 4 * tx;

    float4 bv = *(const float4*)&bias[colb];
    float4 acc0 = bv, acc1 = bv, acc2 = bv, acc3 = bv;

    const float4* Wp = (const float4*)Wsh;
#pragma unroll 4
    for (int k = 0; k < K; k++) {
        float4 a = *(const float4*)&AshT[k * TMP + rid * 4];
        float4 w = Wp[k * NG4 + tx];
        acc0.x = fmaf(a.x, w.x, acc0.x); acc0.y = fmaf(a.x, w.y, acc0.y);
        acc0.z = fmaf(a.x, w.z, acc0.z); acc0.w = fmaf(a.x, w.w, acc0.w);
        acc1.x = fmaf(a.y, w.x, acc1.x); acc1.y = fmaf(a.y, w.y, acc1.y);
        acc1.z = fmaf(a.y, w.z, acc1.z); acc1.w = fmaf(a.y, w.w, acc1.w);
        acc2.x = fmaf(a.z, w.x, acc2.x); acc2.y = fmaf(a.z, w.y, acc2.y);
        acc2.z = fmaf(a.z, w.z, acc2.z); acc2.w = fmaf(a.z, w.w, acc2.w);
        acc3.x = fmaf(a.w, w.x, acc3.x); acc3.y = fmaf(a.w, w.y, acc3.y);
        acc3.z = fmaf(a.w, w.z, acc3.z); acc3.w = fmaf(a.w, w.w, acc3.w);
    }
    float4 accs[4] = {acc0, acc1, acc2, acc3};
#pragma unroll
    for (int r = 0; r < 4; r++)
        *(float4*)&out[(size_t)(rM + rid * 4 + r) * N + colb] = accs[r];
}

// ---------------------------------------------------------------------------
// Fused wavefront RNN v9: FOUR timesteps per global barrier.
// Super-tick s: layer l does t = 4(s-l)+k, k=0..3.
//   step 0: own <- prev ss3, in <- prev ss0, write cur ss0
//   step k: own <- cur ss(k-1), in <- prev ssk, write cur ssk   (k=1..3)
// Per-layer named barrier between sub-steps; ONE global barrier per super-tick.
// 131 super-ticks. Slab layout (per buf, ss): as v8. Smem 8 slabs = 42.8KB.
// ---------------------------------------------------------------------------
#define NBATCH   4
#define NTHREADS 512

// region offsets within a slab (float4 units)
#define O_L0OWN 0    /* 18 */
#define O_L1OWN 18   /* 36 */
#define O_L1IN  54   /* 18 */
#define O_L2OWN 72   /* 72 */
#define O_L2IN  144  /* 36 */
#define O_L3OWN 180  /* 82 */
#define O_L3IN  262  /* 72 */
#define SLABF4  334
#define SLABF   (SLABF4 * 4)

// weights: own rows i = p*C_OWN + r (U), in rows k = p*C_IN + r (W)
template <int C_OWN, int C_IN>
__device__ __forceinline__ void load_wv8(const float* __restrict__ U,
                                         const float* __restrict__ W,
                                         int H, int IN, int jm, int p,
                                         float2 (&wreg)[48]) {
#pragma unroll
    for (int r = 0; r < C_OWN; r++) {
        int i = p * C_OWN + r;
#pragma unroll
        for (int jj = 0; jj < 4; jj++) {
            int j = jm * 4 + jj;
            float v = (j < H && i < H) ? U[i * H + j] : 0.f;
            wreg[r * 4 + jj] = make_float2(v, v);
        }
    }
#pragma unroll
    for (int r = 0; r < C_IN; r++) {
        int k = p * C_IN + r;
#pragma unroll
        for (int jj = 0; jj < 4; jj++) {
            int j = jm * 4 + jj;
            float v = (j < H && k < IN) ? W[k * H + j] : 0.f;
            wreg[(C_OWN + r) * 4 + jj] = make_float2(v, v);
        }
    }
}

template <int C_OWN, int C_IN, int P, bool L0F, bool LAST>
__device__ __forceinline__ void tick_v8(
    const float* ownRd, const float* inRd, float* wr,
    int ownRdOfs, int inRdOfs,
    const float2 (&wreg)[48],
    int p, bool valid, float2 addv,
    int ownWrOfs, int mirWrOfs, bool lastT,
    float* __restrict__ hlast, int hl0, int hl1)
{
    float2 a[8];
#pragma unroll
    for (int k = 0; k < 8; k++) a[k] = make_float2(0.f, 0.f);

    const float4* po = (const float4*)(ownRd + ownRdOfs);
#pragma unroll
    for (int r = 0; r < C_OWN; r++) {
        float4 hh = po[r];
        float2 h01 = make_float2(hh.x, hh.y);
        float2 h23 = make_float2(hh.z, hh.w);
#pragma unroll
        for (int jj = 0; jj < 4; jj++) {
            ffma2_acc(a[2 * jj],     h01, wreg[r * 4 + jj]);
            ffma2_acc(a[2 * jj + 1], h23, wreg[r * 4 + jj]);
        }
    }
    const float4* pi = (const float4*)(inRd + inRdOfs);
#pragma unroll
    for (int r = 0; r < C_IN; r++) {
        float4 hh = pi[r];
        float2 h01 = make_float2(hh.x, hh.y);
        float2 h23 = make_float2(hh.z, hh.w);
#pragma unroll
        for (int jj = 0; jj < 4; jj++) {
            ffma2_acc(a[2 * jj],     h01, wreg[(C_OWN + r) * 4 + jj]);
            ffma2_acc(a[2 * jj + 1], h23, wreg[(C_OWN + r) * 4 + jj]);
        }
    }

    if constexpr (P == 16) {
#pragma unroll
        for (int k = 0; k < 8; k++) a[k] = add2(a[k], sh2(a[k], 8));
    }

    bool s = (p & 4) != 0;
    float2 b[4];
#pragma unroll
    for (int k = 0; k < 4; k++) {
        float2 keep = s ? a[k + 4] : a[k];
        float2 send = s ? a[k] : a[k + 4];
        b[k] = add2(keep, sh2(send, 4));
    }
    s = (p & 2) != 0;
    float2 c[2];
#pragma unroll
    for (int k = 0; k < 2; k++) {
        float2 keep = s ? b[k + 2] : b[k];
        float2 send = s ? b[k] : b[k + 2];
        c[k] = add2(keep, sh2(send, 2));
    }
    s = (p & 1) != 0;
    {
        float2 keep = s ? c[1] : c[0];
        float2 send = s ? c[0] : c[1];
        float2 z = add2(keep, sh2(send, 1));
        if (valid) {
            z = add2(z, addv);
            float t0 = ftanh(z.x);
            float t1 = ftanh(z.y);
            *(float2*)(wr + ownWrOfs) = make_float2(t0, t1);
            if (!LAST) {
                *(float2*)(wr + mirWrOfs) = make_float2(t0, t1);
            } else if (lastT) {
                hlast[hl0] = t0;
                hlast[hl1] = t1;
            }
        }
    }
}

__global__ void __launch_bounds__(NTHREADS, 1)
fused_rnn_kernel(const float* __restrict__ xw0,
                 const float* __restrict__ U0,
                 const float* __restrict__ W1, const float* __restrict__ U1, const float* __restrict__ b1v,
                 const float* __restrict__ W2, const float* __restrict__ U2, const float* __restrict__ b2v,
                 const float* __restrict__ W3, const float* __restrict__ U3, const float* __restrict__ b3v,
                 float* __restrict__ hlast)
{
    __shared__ __align__(16) float4 vin[8 * SLABF4];   // (buf, ss0..3) slabs
    float* vinF = (float*)vin;

    const int tid  = threadIdx.x;
    const int lane = tid & 31;
    const int wid  = tid >> 5;
    const int bbase = blockIdx.x * NBATCH;

    // SMSP-balanced warp->layer map (wid&3 = SMSP):
    // L3: w0-7,w11 | L2: w8,9,10,15 | L1: w13,14 | L0: w12
    int layer, lwarp;
    if (wid <= 7)        { layer = 3; lwarp = wid; }
    else if (wid == 11)  { layer = 3; lwarp = 8; }
    else if (wid <= 10)  { layer = 2; lwarp = wid - 8; }
    else if (wid == 15)  { layer = 2; lwarp = 3; }
    else if (wid >= 13)  { layer = 1; lwarp = wid - 13; }
    else                 { layer = 0; lwarp = 0; }  // wid == 12

    int p = 0, unit = 0;
    bool valid = false;
    int ownRdOfs = 0, inRdOfs = 0, ownWrOfs = 0, mirWrOfs = 0, hl0 = 0, hl1 = 0;
    float2 bias2 = make_float2(0.f, 0.f);
    float2 wreg[48];
#pragma unroll
    for (int k = 0; k < 48; k++) wreg[k] = make_float2(0.f, 0.f);

    const int slot = lwarp * 32 + lane;

    if (layer == 3) {
        int jm = slot >> 4; p = slot & 15;      // 18 groups, P=16
        int q = p & 7;
        int jj = (q >> 1) & 3, bp = q & 1;
        unit = jm * 4 + jj;
        valid = (unit < 70) && (p < 8);
        load_wv8<5, 4>(U3, W3, 70, 64, jm, p, wreg);
        ownRdOfs = 4 * (O_L3OWN + 5 * p + (p >> 3));
        inRdOfs  = 4 * (O_L3IN  + 4 * p + (p >> 1));
        ownWrOfs = 4 * (O_L3OWN + unit + ((unit / 5) >> 3)) + 2 * bp;
        hl0 = (bbase + 2 * bp) * 70 + unit;
        hl1 = (bbase + 2 * bp + 1) * 70 + unit;
        if (unit < 70) { float bb = b3v[unit]; bias2 = make_float2(bb, bb); }
    } else if (layer == 2) {
        int jm = slot >> 3; p = slot & 7;       // 16 groups, P=8
        int jj = (p >> 1) & 3, bp = p & 1;
        unit = jm * 4 + jj;
        valid = true;
        load_wv8<8, 4>(U2, W2, 64, 32, jm, p, wreg);
        ownRdOfs = 4 * (O_L2OWN + 9 * p);
        inRdOfs  = 4 * (O_L2IN  + 4 * p + (p >> 1));
        ownWrOfs = 4 * (O_L2OWN + unit + unit / 8) + 2 * bp;
        mirWrOfs = 4 * (O_L3IN + unit + ((unit / 4) >> 1)) + 2 * bp;
        float bb = b2v[unit]; bias2 = make_float2(bb, bb);
    } else if (layer == 1) {
        int jm = slot >> 3; p = slot & 7;       // 8 groups, P=8
        int jj = (p >> 1) & 3, bp = p & 1;
        unit = jm * 4 + jj;
        valid = true;
        load_wv8<4, 2>(U1, W1, 32, 16, jm, p, wreg);
        ownRdOfs = 4 * (O_L1OWN + 4 * p + (p >> 1));
        inRdOfs  = 4 * (O_L1IN  + 2 * p + (p >> 2));
        ownWrOfs = 4 * (O_L1OWN + unit + ((unit / 4) >> 1)) + 2 * bp;
        mirWrOfs = 4 * (O_L2IN + unit + ((unit / 4) >> 1)) + 2 * bp;
        float bb = b1v[unit]; bias2 = make_float2(bb, bb);
    } else {
        int jm = lane >> 3; p = lane & 7;       // 4 groups, P=8
        int jj = (p >> 1) & 3, bp = p & 1;
        unit = jm * 4 + jj;
        valid = true;
        load_wv8<2, 0>(U0, U0, 16, 0, jm, p, wreg);   // W unused (IN=0)
        ownRdOfs = 4 * (O_L0OWN + 2 * p + (p >> 2));
        inRdOfs  = 0;
        ownWrOfs = 4 * (O_L0OWN + unit + ((unit / 2) >> 2)) + 2 * bp;
        mirWrOfs = 4 * (O_L1IN + unit + ((unit / 2) >> 2)) + 2 * bp;
        hl0 = (bbase + 2 * bp) * 16 + unit;     // xw0 gather offsets
        hl1 = (bbase + 2 * bp + 1) * 16 + unit;
    }

    // zero all 8 slabs
    for (int i = tid; i < 8 * SLABF4; i += NTHREADS)
        ((float4*)vin)[i] = make_float4(0.f, 0.f, 0.f, 0.f);

    // L0 xw double buffer: xa[k] = x(4s+k) in use, xb[k] = prefetch for s+1
    float2 xa[4], xb[4];
#pragma unroll
    for (int k = 0; k < 4; k++) xa[k] = xb[k] = make_float2(0.f, 0.f);
    if (layer == 0) {
#pragma unroll
        for (int k = 0; k < 4; k++) {
            size_t o = (size_t)k * 8192;
            xa[k] = make_float2(xw0[o + hl0], xw0[o + hl1]);
        }
    }
    __syncthreads();

    for (int s = 0; s < 131; s++) {
        const int cur = s & 1, prev = cur ^ 1;
        float* P0 = vinF + (prev * 4 + 0) * SLABF;
        float* P1 = vinF + (prev * 4 + 1) * SLABF;
        float* P2 = vinF + (prev * 4 + 2) * SLABF;
        float* P3 = vinF + (prev * 4 + 3) * SLABF;
        float* C0 = vinF + (cur * 4 + 0) * SLABF;
        float* C1 = vinF + (cur * 4 + 1) * SLABF;
        float* C2 = vinF + (cur * 4 + 2) * SLABF;
        float* C3 = vinF + (cur * 4 + 3) * SLABF;
        const int tl = s - layer;
        const bool active = (tl >= 0) && (tl < 128);

        // L0: prefetch next super-tick's xw group early (covered by this tick)
        if (layer == 0 && s + 1 < 128) {
            size_t base = (size_t)(4 * (s + 1)) * 8192;
#pragma unroll
            for (int k = 0; k < 4; k++) {
                size_t o = base + (size_t)k * 8192;
                xb[k] = make_float2(xw0[o + hl0], xw0[o + hl1]);
            }
        }

#define RUN_STEP(OWNRD, INRD, WRDST, XK, LASTF)                                   \
        if (active) {                                                            \
            if (layer == 3)                                                      \
                tick_v8<5, 4, 16, false, true>(OWNRD, INRD, WRDST, ownRdOfs,     \
                    inRdOfs, wreg, p, valid, bias2, ownWrOfs, mirWrOfs,          \
                    LASTF, hlast, hl0, hl1);                                     \
            else if (layer == 2)                                                 \
                tick_v8<8, 4, 8, false, false>(OWNRD, INRD, WRDST, ownRdOfs,     \
                    inRdOfs, wreg, p, valid, bias2, ownWrOfs, mirWrOfs,          \
                    false, hlast, 0, 0);                                         \
            else if (layer == 1)                                                 \
                tick_v8<4, 2, 8, false, false>(OWNRD, INRD, WRDST, ownRdOfs,     \
                    inRdOfs, wreg, p, valid, bias2, ownWrOfs, mirWrOfs,          \
                    false, hlast, 0, 0);                                         \
            else                                                                 \
                tick_v8<2, 0, 8, true, false>(OWNRD, INRD, WRDST, ownRdOfs,      \
                    inRdOfs, wreg, p, valid, XK, ownWrOfs, mirWrOfs,             \
                    false, hlast, 0, 0);                                         \
        }

#define LBAR()                                                                   \
        if (layer == 3)      barn(1, 288);                                       \
        else if (layer == 2) barn(2, 128);                                       \
        else if (layer == 1) barn(3, 64);                                        \
        else                 __syncwarp();

        RUN_STEP(P3, P0, C0, xa[0], false)
        LBAR()
        RUN_STEP(C0, P1, C1, xa[1], false)
        LBAR()
        RUN_STEP(C1, P2, C2, xa[2], false)
        LBAR()
        RUN_STEP(C2, P3, C3, xa[3], (tl == 127))

#undef RUN_STEP
#undef LBAR

        // rotate L0 xw double buffer
        if (layer == 0) {
#pragma unroll
            for (int k = 0; k < 4; k++) xa[k] = xb[k];
        }

        __syncthreads();
    }
}

// ---------------------------------------------------------------------------
// Dense (70 -> 5) + softmax, smem-staged. grid 4 x block 128.
// ---------------------------------------------------------------------------
__global__ void __launch_bounds__(128)
dense_softmax_kernel(const float* __restrict__ h,
                     const float* __restrict__ Wd,
                     const float* __restrict__ bd,
                     float* __restrict__ out) {
    __shared__ float hs[128 * 70];
    __shared__ float Wds[70 * 5 + 5];

    const int tid = threadIdx.x;
    const int b0  = blockIdx.x * 128;

    for (int idx = tid; idx < 128 * 70; idx += 128)
        hs[idx] = h[(size_t)b0 * 70 + idx];
    for (int idx = tid; idx < 355; idx += 128)
        Wds[idx] = (idx < 350) ? Wd[idx] : bd[idx - 350];
    __syncthreads();

    float l[5];
#pragma unroll
    for (int c = 0; c < 5; c++) l[c] = Wds[350 + c];
#pragma unroll 2
    for (int k = 0; k < 70; k++) {
        float hv = hs[tid * 70 + k];
#pragma unroll
        for (int c = 0; c < 5; c++) l[c] = fmaf(hv, Wds[k * 5 + c], l[c]);
    }
    float m = l[0];
#pragma unroll
    for (int c = 1; c < 5; c++) m = fmaxf(m, l[c]);
    float s = 0.f;
#pragma unroll
    for (int c = 0; c < 5; c++) { l[c] = expf(l[c] - m); s += l[c]; }
    float inv = 1.f / s;
#pragma unroll
    for (int c = 0; c < 5; c++) out[(size_t)(b0 + tid) * 5 + c] = l[c] * inv;
}

// ---------------------------------------------------------------------------
extern "C" void kernel_launch(void* const* d_in, const int* in_sizes, int n_in,
                              void* d_out, int out_size) {
    const float* x  = (const float*)d_in[0];
    const float* W0 = (const float*)d_in[1];
    const float* U0 = (const float*)d_in[2];
    const float* b0 = (const float*)d_in[3];
    const float* W1 = (const float*)d_in[4];
    const float* U1 = (const float*)d_in[5];
    const float* b1 = (const float*)d_in[6];
    const float* W2 = (const float*)d_in[7];
    const float* U2 = (const float*)d_in[8];
    const float* b2 = (const float*)d_in[9];
    const float* W3 = (const float*)d_in[10];
    const float* U3 = (const float*)d_in[11];
    const float* b3 = (const float*)d_in[12];
    const float* Wd = (const float*)d_in[13];
    const float* bd = (const float*)d_in[14];
    float* out = (float*)d_out;

    static float* xw0 = nullptr;
    static float* hlast = nullptr;
    static float* dummy = nullptr;
    if (!xw0) {
        cudaGetSymbolAddress((void**)&xw0, g_xw0);
        cudaGetSymbolAddress((void**)&hlast, g_hlast);
        cudaGetSymbolAddress((void**)&dummy, g_dummy);
    }

    const int M = T_ * B_;  // 262144

    // two dummies: the profiler captures the 4th launch -> fused_rnn_kernel
    dummy_kernel<<<1, 32>>>(dummy);
    dummy_kernel<<<1, 32>>>(dummy);

    gemm0_kernel<78, 16, 128><<<M / 128, 4 * 32>>>(x, W0, b0, xw0);

    fused_rnn_kernel<<<B_ / NBATCH, NTHREADS>>>(xw0, U0,
                                                W1, U1, b1,
                                                W2, U2, b2,
                                                W3, U3, b3,
                                                hlast);

    dense_softmax_kernel<<<4, 128>>>(hlast, Wd, bd, out);
}